// round 2
// baseline (speedup 1.0000x reference)
#include <cuda_runtime.h>
#include <cuda_bf16.h>

// Label-smoothing KL loss, closed form:
//   per valid row r:  kl_r = c*log(c) + K*s*log(s) - c*lt - s*(S_r - lt [- lz])
// where S_r = sum_v log(x[r,v]+eps), lt = log(x[r,t]+eps), lz = log(x[r, V-100]+eps),
// K = V-2 (or V-1 if t == V-100, where the lz term also drops).
// Answer = sum over valid rows.
//
// NOTE: targets are int32 on the wire (JAX x64 disabled -> jnp.int64 lowers to i32).

#define LS_MAX_ROWS 65536

__device__ float g_row_contrib[LS_MAX_ROWS];

// Fast natural log for normal positive floats (v >= 1e-12 here, no subnormals).
// Mantissa reduced to [2/3, 4/3), degree-7 Taylor of ln(1+f), |abs err| < 2e-5.
__device__ __forceinline__ float fast_log(float v) {
    int i = __float_as_int(v);
    int e = (i - 0x3f2aaaab) & 0xff800000;
    float m = __int_as_float(i - e);
    float f = m - 1.0f;
    float p = fmaf(0.142857143f, f, -0.166666667f);
    p = fmaf(p, f, 0.20f);
    p = fmaf(p, f, -0.25f);
    p = fmaf(p, f, 0.333333333f);
    p = fmaf(p, f, -0.5f);
    p = fmaf(p, f, 1.0f);
    return fmaf((float)(e >> 23), 0.693147180559945f, p * f);
}

template <int BLOCK>
__global__ void __launch_bounds__(BLOCK)
ls_row_kernel(const float* __restrict__ x,
              const int* __restrict__ tgt,
              int V) {
    const int row = blockIdx.x;
    const float* __restrict__ px = x + (size_t)row * (size_t)V;

    // Per-thread partial: psum = sum of ln(mantissa) terms (FMA pipe),
    //                     esum = sum of exponents (ALU pipe, exact int).
    float psum = 0.0f;
    int esum = 0;

    #pragma unroll 4
    for (int j = threadIdx.x; j < V; j += BLOCK) {
        float v = __ldg(px + j) + 1e-12f;
        int i = __float_as_int(v);
        int e = (i - 0x3f2aaaab) & 0xff800000;
        float m = __int_as_float(i - e);
        esum += (e >> 23);
        float f = m - 1.0f;
        float p = fmaf(0.142857143f, f, -0.166666667f);
        p = fmaf(p, f, 0.20f);
        p = fmaf(p, f, -0.25f);
        p = fmaf(p, f, 0.333333333f);
        p = fmaf(p, f, -0.5f);
        p = fmaf(p, f, 1.0f);
        psum = fmaf(p, f, psum);
    }

    // Warp reduce
    #pragma unroll
    for (int o = 16; o > 0; o >>= 1) {
        psum += __shfl_down_sync(0xffffffffu, psum, o);
        esum += __shfl_down_sync(0xffffffffu, esum, o);
    }

    constexpr int NW = BLOCK / 32;
    __shared__ float sf[NW];
    __shared__ int   se[NW];
    const int lane = threadIdx.x & 31;
    const int wid  = threadIdx.x >> 5;
    if (lane == 0) { sf[wid] = psum; se[wid] = esum; }
    __syncthreads();

    if (threadIdx.x == 0) {
        float pt = 0.0f;
        int   et = 0;
        #pragma unroll
        for (int w = 0; w < NW; w++) { pt += sf[w]; et += se[w]; }

        // S_r = sum ln(x+eps) over the row
        float S = fmaf((float)et, 0.693147180559945f, pt);

        int t = tgt[row];
        float contrib = 0.0f;
        if (t != -100 && t >= 0 && t < V) {     // bounds guard: never gather OOB
            const int zidx = V - 100;           // JAX .at[-100] wraps to V-100
            const float c = 0.9f;
            const float logc = -0.105360515657826f;   // ln(0.9)
            const float s = 0.1f / (float)(V - 1);
            const float logs = fast_log(s);           // ln(s)

            float lt = fast_log(__ldg(px + t) + 1e-12f);
            if (t == zidx) {
                contrib = c * logc + (float)(V - 1) * s * logs
                        - c * lt - s * (S - lt);
            } else {
                float lz = fast_log(__ldg(px + zidx) + 1e-12f);
                contrib = c * logc + (float)(V - 2) * s * logs
                        - c * lt - s * (S - lt - lz);
            }
        }
        g_row_contrib[row] = contrib;
    }
}

__global__ void __launch_bounds__(1024)
ls_final_reduce(float* __restrict__ out, int N) {
    float s = 0.0f;
    for (int i = threadIdx.x; i < N; i += 1024)
        s += g_row_contrib[i];

    #pragma unroll
    for (int o = 16; o > 0; o >>= 1)
        s += __shfl_down_sync(0xffffffffu, s, o);

    __shared__ float sw[32];
    const int lane = threadIdx.x & 31;
    const int wid  = threadIdx.x >> 5;
    if (lane == 0) sw[wid] = s;
    __syncthreads();
    if (wid == 0) {
        float v = sw[lane];
        #pragma unroll
        for (int o = 16; o > 0; o >>= 1)
            v += __shfl_down_sync(0xffffffffu, v, o);
        if (lane == 0) out[0] = v;
    }
}

extern "C" void kernel_launch(void* const* d_in, const int* in_sizes, int n_in,
                              void* d_out, int out_size) {
    const float* x = (const float*)d_in[0];
    const int* tgt = (const int*)d_in[1];
    const int N = in_sizes[1];
    const int V = in_sizes[0] / N;

    int rows = N > LS_MAX_ROWS ? LS_MAX_ROWS : N;
    ls_row_kernel<256><<<rows, 256>>>(x, tgt, V);
    ls_final_reduce<<<1, 1024>>>((float*)d_out, rows);
}